// round 9
// baseline (speedup 1.0000x reference)
#include <cuda_runtime.h>
#include <cuda_fp16.h>

#define HID 256
#define G4  1024
#define NE  64
#define BAT 256
#define NSTEP 6
#define RK  16
#define NBLK 128
#define NTHR 512
#define NBAR 12

// ---------------- scratch (allocation-free: device globals) ----------------
__device__ __align__(16) float   g_xg[NE * G4];      // fp32 gate-interleaved [j][k][4]
__device__ __align__(16) uint2   g_xgh[NE * HID];    // fp16 (i,f)(g,o) packed
__device__ __align__(16) __half2 g_whh2[128 * G4];   // PW[kp][m] = (WhhT[2kp][m], WhhT[2kp+1][m])
__device__ __align__(16) __half2 g_wm2[128 * HID];   // PM[kp][m]
__device__ __align__(16) float   g_h0v[NE * HID];
__device__ __align__(16) float   g_c0v[NE * HID];
__device__ __align__(16) float   g_sout[NE * RK];
__device__ __align__(16) float   g_hcur[BAT * HID];  // current h, all batches (mutable)
__device__ __align__(16) float   g_hg[BAT * G4];     // h @ WhhT, all batches (mutable)
__device__ unsigned g_bcnt[NBAR];                    // self-resetting arrive counts
__device__ unsigned g_brel[NBAR];                    // monotonic release generations

// ---------------- transcendentals ------------------------------------------
__device__ __forceinline__ float tap(float x){ float y; asm("tanh.approx.f32 %0,%1;" : "=f"(y) : "f"(x)); return y; }
__device__ __forceinline__ float frcp(float x){ float y; asm("rcp.approx.f32 %0,%1;" : "=f"(y) : "f"(x)); return y; }
__device__ __forceinline__ float sigm(float x){ return fmaf(0.5f, tap(0.5f * x), 0.5f); }
__device__ __forceinline__ float2 h2f(__half2 h){ return __half22float2(h); }

// ---------------- grid barrier (replay-safe, all-atomic) --------------------
// gen snapshot BEFORE arrive (fence-ordered). Winner resets count via
// atomicExch (same L2-atomic path as the arrivals — no ST/ATOM mixed-path
// race), fences, then bumps the monotonic release generation.
__device__ __forceinline__ void gbar(int idx)
{
    __threadfence();
    __syncthreads();
    if (threadIdx.x == 0) {
        volatile unsigned* relv = &g_brel[idx];
        const unsigned gen = *relv;
        __threadfence();                       // order gen read before arrive
        const unsigned old = atomicAdd(&g_bcnt[idx], 1u);
        if (old == NBLK - 1) {
            atomicExch(&g_bcnt[idx], 0u);
            __threadfence();
            atomicAdd(&g_brel[idx], 1u);
        } else {
            while (*relv == gen) __nanosleep(64);
        }
    }
    __syncthreads();
}

// ============================================================================
__global__ __launch_bounds__(NTHR) void k_mega(
    const int*   __restrict__ xidx,
    const float* __restrict__ emb,  const float* __restrict__ Wih,
    const float* __restrict__ bih,  const float* __restrict__ bhh,
    const float* __restrict__ Whh,  const float* __restrict__ Wm,
    const float* __restrict__ Wf,   const float* __restrict__ bf,
    const float* __restrict__ bm,
    const float* __restrict__ Wl,   const float* __restrict__ bl,
    float* __restrict__ out)
{
    const int bid = blockIdx.x, t = threadIdx.x;
    const int half = t >> 8, tt = t & 255;
    const int b0 = bid * 2;

    // persistent smem
    __shared__ __align__(16) float sh_h[2][HID];
    __shared__ __align__(16) float sh_c[2][HID];
    __shared__ __align__(16) float s_cur[2][HID];
    __shared__ float st_tot[2][RK];
    __shared__ float s_rcl[RK];
    // phase-scratch union
    __shared__ __align__(16) union {
        float ht[32 * 257];                       // GEMM h-tile (pad 257: bank-safe)
        struct { float hs[4][HID]; float md[8][HID]; } cm;
        struct { float As[16][34]; float Bs[16][68]; } pg;  // prep xg-GEMM
        float T[64 * 65];                          // prep transpose tile
        float sh0[HID];                            // prep h0
    } S;

    // ======================= P0: prep (xg GEMM / weight packs) =============
    if (bid < 32) {
        const int tx = t & 15, ty = (t & 255) >> 4;
        const int jb0 = (bid & 1) * 32;
        const int m0 = (bid >> 1) * 64;
        float acc[2][4] = {};
        for (int k0 = 0; k0 < HID; k0 += 16) {
            if (t < 128) {
                const int r = t >> 2, c = (t & 3) * 4;
                const float4 v = *(const float4*)&emb[(jb0 + r) * HID + k0 + c];
                S.pg.As[c+0][r] = v.x; S.pg.As[c+1][r] = v.y; S.pg.As[c+2][r] = v.z; S.pg.As[c+3][r] = v.w;
            }
            if (t < 256) {
                const int r = t >> 2, c = (t & 3) * 4;
                const float4 v = *(const float4*)&Wih[(m0 + r) * HID + k0 + c];
                S.pg.Bs[c+0][r] = v.x; S.pg.Bs[c+1][r] = v.y; S.pg.Bs[c+2][r] = v.z; S.pg.Bs[c+3][r] = v.w;
            }
            __syncthreads();
            if (t < 256) {
                #pragma unroll
                for (int kk = 0; kk < 16; kk++) {
                    const float2 a = *(const float2*)&S.pg.As[kk][2 * ty];
                    const float4 bv = *(const float4*)&S.pg.Bs[kk][4 * tx];
                    acc[0][0] = fmaf(a.x, bv.x, acc[0][0]); acc[0][1] = fmaf(a.x, bv.y, acc[0][1]);
                    acc[0][2] = fmaf(a.x, bv.z, acc[0][2]); acc[0][3] = fmaf(a.x, bv.w, acc[0][3]);
                    acc[1][0] = fmaf(a.y, bv.x, acc[1][0]); acc[1][1] = fmaf(a.y, bv.y, acc[1][1]);
                    acc[1][2] = fmaf(a.y, bv.z, acc[1][2]); acc[1][3] = fmaf(a.y, bv.w, acc[1][3]);
                }
            }
            __syncthreads();
        }
        if (t < 256) {
            const int mc0 = m0 + 4 * tx;
            const int gate = mc0 >> 8, kc0 = mc0 & 255;
            float bias[4];
            #pragma unroll
            for (int jj = 0; jj < 4; jj++) bias[jj] = bih[mc0 + jj] + bhh[mc0 + jj];
            #pragma unroll
            for (int i = 0; i < 2; i++) {
                const int jr = jb0 + 2 * ty + i;
                #pragma unroll
                for (int jj = 0; jj < 4; jj++)
                    g_xg[jr * G4 + 4 * (kc0 + jj) + gate] = acc[i][jj] + bias[jj];
            }
        }
    } else if (bid < 112) {
        const bool isWhh = (bid < 96);
        const int tid = isWhh ? (bid - 32) : (bid - 96);
        const int mi = isWhh ? (tid & 15) : (tid & 3);
        const int ki = isWhh ? (tid >> 4) : (tid >> 2);
        const float* __restrict__ src = isWhh ? Whh : Wm;
        if (t < 256) {
            const int c4 = (t & 15) * 4;
            const int r0 = t >> 4;
            #pragma unroll
            for (int i = 0; i < 4; i++) {
                const float4 v = *(const float4*)&src[(mi * 64 + r0 + 16 * i) * HID + ki * 64 + c4];
                float* Trow = S.T + (r0 + 16 * i) * 65;
                Trow[c4+0] = v.x; Trow[c4+1] = v.y; Trow[c4+2] = v.z; Trow[c4+3] = v.w;
            }
        }
        __syncthreads();
        if (t < 256) {
            const int m_l = t & 63, kp0 = (t >> 6) & 3;
            const int rowlen = isWhh ? G4 : HID;
            __half2* __restrict__ dst = isWhh ? g_whh2 : g_wm2;
            #pragma unroll
            for (int i = 0; i < 8; i++) {
                const int kpl = kp0 + 4 * i;
                const __half2 h2 = __floats2half2_rn(S.T[m_l * 65 + 2 * kpl], S.T[m_l * 65 + 2 * kpl + 1]);
                dst[(ki * 32 + kpl) * rowlen + mi * 64 + m_l] = h2;
            }
        }
    }
    gbar(0);

    // ======================= P1: h0/c0/sout (blocks 0..63) ==================
    if (bid < 64) {
        const int j = bid;
        if (t < 256) {
            const float4 x4 = __ldcg(((const float4*)g_xg) + j * HID + t);   // (i,f,g,o)
            union { __half2 h2[2]; uint2 u; } p;
            p.h2[0] = __floats2half2_rn(x4.x, x4.y);
            p.h2[1] = __floats2half2_rn(x4.z, x4.w);
            g_xgh[j * HID + t] = p.u;
            const float c0 = sigm(x4.x) * tap(x4.z);
            const float h0 = sigm(x4.w) * tap(c0);
            g_c0v[j * HID + t] = c0;
            g_h0v[j * HID + t] = h0;
            S.sh0[t] = h0;
        }
        __syncthreads();
        if (t < 256) {
            const int w = t >> 5, l = t & 31;
            #pragma unroll
            for (int rr = 0; rr < 2; rr++) {
                const int r = w + 8 * rr;
                float a = 0.f;
                #pragma unroll
                for (int q = 0; q < 8; q++) a = fmaf(S.sh0[l + 32 * q], Wf[r * HID + l + 32 * q], a);
                a += __shfl_xor_sync(0xFFFFFFFFu, a, 16);
                a += __shfl_xor_sync(0xFFFFFFFFu, a, 8);
                a += __shfl_xor_sync(0xFFFFFFFFu, a, 4);
                a += __shfl_xor_sync(0xFFFFFFFFu, a, 2);
                a += __shfl_xor_sync(0xFFFFFFFFu, a, 1);
                if (l == 0) g_sout[j * RK + r] = a + bf[r];
            }
        }
    }
    gbar(1);

    // ======================= P2: per-block init =============================
    if (t < RK) {
        float s = 0.f;
        #pragma unroll 8
        for (int j = 0; j < NE; j++) s += __ldcg(&g_sout[j * RK + t]);
        s_rcl[t] = 1.0f / s;
    }
    {
        const int sel = xidx[(b0 + half) * NSTEP + 0];
        const float hv = __ldcg(&g_h0v[sel * HID + tt]);
        sh_h[half][tt] = hv;
        sh_c[half][tt] = __ldcg(&g_c0v[sel * HID + tt]);
        g_hcur[(b0 + half) * HID + tt] = hv;
    }
    __syncthreads();
    if (t < 2 * RK) {
        const int b = t >> 4, r = t & 15;
        const int sel = xidx[(b0 + b) * NSTEP + 0];
        st_tot[b][r] = __ldcg(&g_sout[sel * RK + r]) * s_rcl[r];
    }
    gbar(2);

    // ======================= step loop ======================================
    for (int s = 1; s < NSTEP; s++) {
        // ---- cooperative GEMM: g_hg = g_hcur @ WhhT; tile 32b x 64m ----
        {
            const int bg0 = (bid >> 4) * 32;
            const int m0  = (bid & 15) * 64;
            #pragma unroll
            for (int i = 0; i < 4; i++) {
                const int e = t + NTHR * i;               // 0..2047 float4 slots
                const int row = e >> 6, col4 = (e & 63) * 4;
                const float4 v = __ldcg((const float4*)&g_hcur[(bg0 + row) * HID + col4]);
                float* d = S.ht + row * 257 + col4;
                d[0] = v.x; d[1] = v.y; d[2] = v.z; d[3] = v.w;
            }
            __syncthreads();
            const int tb = t & 31, tm = t >> 5;           // warp: uniform tm
            const int mb = m0 + tm * 4;
            const float* hrow = S.ht + tb * 257;
            float4 ac = {0.f, 0.f, 0.f, 0.f};
            #pragma unroll 4
            for (int kp = 0; kp < 128; kp++) {
                const uint4 w = *(const uint4*)&g_whh2[kp * G4 + mb];
                const float hx = hrow[2 * kp], hy = hrow[2 * kp + 1];
                const float2 p0 = h2f(*(const __half2*)&w.x);
                const float2 p1 = h2f(*(const __half2*)&w.y);
                const float2 p2 = h2f(*(const __half2*)&w.z);
                const float2 p3 = h2f(*(const __half2*)&w.w);
                ac.x = fmaf(hx, p0.x, fmaf(hy, p0.y, ac.x));
                ac.y = fmaf(hx, p1.x, fmaf(hy, p1.y, ac.y));
                ac.z = fmaf(hx, p2.x, fmaf(hy, p2.y, ac.z));
                ac.w = fmaf(hx, p3.x, fmaf(hy, p3.y, ac.w));
            }
            *(float4*)&g_hg[(bg0 + tb) * G4 + mb] = ac;
        }
        gbar(3 + 2 * (s - 1));

        // ---- CELL: own 2 batches, j-split by half, k = tt ----
        const int selb0 = xidx[b0 * NSTEP + s];
        const int selb1 = xidx[(b0 + 1) * NSTEP + s];
        {
            const int k = tt;
            const float* hg0 = g_hg + (b0 + 0) * G4;
            const float* hg1 = g_hg + (b0 + 1) * G4;
            const float hgI0 = __ldcg(hg0 + k),           hgF0 = __ldcg(hg0 + HID + k);
            const float hgG0 = __ldcg(hg0 + 2 * HID + k), hgO0 = __ldcg(hg0 + 3 * HID + k);
            const float hgI1 = __ldcg(hg1 + k),           hgF1 = __ldcg(hg1 + HID + k);
            const float hgG1 = __ldcg(hg1 + 2 * HID + k), hgO1 = __ldcg(hg1 + 3 * HID + k);
            const float cp0 = sh_c[0][k], cp1 = sh_c[1][k];
            __syncthreads();               // reads done before owners overwrite
            float hs0 = 0.f, hs1 = 0.f, hv0 = 0.f, cv0 = 0.f, hv1 = 0.f, cv1 = 0.f;
            const int jb = half * 32;
            #pragma unroll 4
            for (int j = jb; j < jb + 32; j++) {
                const uint2 u = g_xgh[j * HID + k];
                const float2 vif = h2f(*(const __half2*)&u.x);
                const float2 vgo = h2f(*(const __half2*)&u.y);
                {
                    const float iv = sigm(vif.x + hgI0);
                    const float fv = sigm(vif.y + hgF0);
                    const float gv = tap (vgo.x + hgG0);
                    const float ov = sigm(vgo.y + hgO0);
                    const float cn = fmaf(fv, cp0, iv * gv);
                    const float hn = ov * tap(cn);
                    hs0 += hn;
                    if (j == selb0) { hv0 = hn; cv0 = cn; }
                }
                {
                    const float iv = sigm(vif.x + hgI1);
                    const float fv = sigm(vif.y + hgF1);
                    const float gv = tap (vgo.x + hgG1);
                    const float ov = sigm(vgo.y + hgO1);
                    const float cn = fmaf(fv, cp1, iv * gv);
                    const float hn = ov * tap(cn);
                    hs1 += hn;
                    if (j == selb1) { hv1 = hn; cv1 = cn; }
                }
            }
            S.cm.hs[half * 2 + 0][k] = hs0;
            S.cm.hs[half * 2 + 1][k] = hs1;
            if ((selb0 >> 5) == half) {
                sh_h[0][k] = hv0; sh_c[0][k] = cv0;
                if (s < NSTEP - 1) g_hcur[(b0 + 0) * HID + k] = hv0;
            }
            if ((selb1 >> 5) == half) {
                sh_h[1][k] = hv1; sh_c[1][k] = cv1;
                if (s < NSTEP - 1) g_hcur[(b0 + 1) * HID + k] = hv1;
            }
        }
        __syncthreads();
        {   // combine hsum halves -> S.cm.hs[b][k]
            const int b = t >> 8, k2 = t & 255;
            S.cm.hs[b][k2] += S.cm.hs[2 + b][k2];
        }
        __syncthreads();

        if (s < NSTEP - 1) {
            // ---- MID: cur = (hsel.Wm+bm)/(hsum.Wm+64bm); total @= cur ----
            const int kpb = half * 64;
            const int m = tt;
            float n0 = 0.f, n1 = 0.f, d0 = 0.f, d1 = 0.f;
            #pragma unroll 4
            for (int kp = 0; kp < 64; kp++) {
                const float2 w = h2f(g_wm2[(kpb + kp) * HID + m]);
                const float2 hA = *(const float2*)&sh_h[0][2 * (kpb + kp)];
                const float2 hB = *(const float2*)&sh_h[1][2 * (kpb + kp)];
                const float2 uA = *(const float2*)&S.cm.hs[0][2 * (kpb + kp)];
                const float2 uB = *(const float2*)&S.cm.hs[1][2 * (kpb + kp)];
                n0 = fmaf(w.x, hA.x, fmaf(w.y, hA.y, n0));
                n1 = fmaf(w.x, hB.x, fmaf(w.y, hB.y, n1));
                d0 = fmaf(w.x, uA.x, fmaf(w.y, uA.y, d0));
                d1 = fmaf(w.x, uB.x, fmaf(w.y, uB.y, d1));
            }
            S.cm.md[half * 4 + 0][m] = n0;
            S.cm.md[half * 4 + 1][m] = n1;
            S.cm.md[half * 4 + 2][m] = d0;
            S.cm.md[half * 4 + 3][m] = d1;
            __syncthreads();
            if (half == 0) {
                const float n0f = S.cm.md[0][tt] + S.cm.md[4][tt];
                const float n1f = S.cm.md[1][tt] + S.cm.md[5][tt];
                const float d0f = S.cm.md[2][tt] + S.cm.md[6][tt];
                const float d1f = S.cm.md[3][tt] + S.cm.md[7][tt];
                const float bmv = bm[tt];
                s_cur[0][tt] = (n0f + bmv) * frcp(d0f + 64.0f * bmv);
                s_cur[1][tt] = (n1f + bmv) * frcp(d1f + 64.0f * bmv);
            }
            __syncthreads();
            float ntot = 0.f;
            const int ub = t >> 4, ur = t & 15;
            if (t < 32) {
                #pragma unroll
                for (int r1 = 0; r1 < RK; r1++)
                    ntot = fmaf(st_tot[ub][r1], s_cur[ub][r1 * RK + ur], ntot);
            }
            __syncthreads();
            if (t < 32) st_tot[ub][ur] = ntot;
            gbar(4 + 2 * (s - 1));
        } else {
            // ---- FINAL: out[b] = total . (hsel.Wl+bl)/(hsum.Wl+64bl) ----
            if (t < 64) {
                const int b = t >> 5, l = t & 31;
                const int r = l & 15, role = l >> 4;
                const float* __restrict__ src = role ? &S.cm.hs[b][0] : &sh_h[b][0];
                float acc = 0.f;
                #pragma unroll 8
                for (int kk = 0; kk < HID; kk++)
                    acc = fmaf(Wl[r * HID + kk], src[kk], acc);
                acc += (role ? 64.0f : 1.0f) * bl[r];
                const float den = __shfl_down_sync(0xFFFFFFFFu, acc, 16);
                float v = 0.f;
                if (!role) v = st_tot[b][r] * acc * frcp(den);
                v += __shfl_xor_sync(0xFFFFFFFFu, v, 8);
                v += __shfl_xor_sync(0xFFFFFFFFu, v, 4);
                v += __shfl_xor_sync(0xFFFFFFFFu, v, 2);
                v += __shfl_xor_sync(0xFFFFFFFFu, v, 1);
                if (l == 0) out[b0 + b] = v;
            }
        }
    }
}

// ============================================================================
extern "C" void kernel_launch(void* const* d_in, const int* in_sizes, int n_in,
                              void* d_out, int out_size)
{
    (void)in_sizes; (void)n_in; (void)out_size;
    const int*   x_idx = (const int*)  d_in[0];
    const float* emb   = (const float*)d_in[1];
    const float* Wih   = (const float*)d_in[2];
    const float* Whh   = (const float*)d_in[3];
    const float* bih   = (const float*)d_in[4];
    const float* bhh   = (const float*)d_in[5];
    const float* Wf    = (const float*)d_in[6];
    const float* bf    = (const float*)d_in[7];
    const float* Wm    = (const float*)d_in[8];
    const float* bm    = (const float*)d_in[9];
    const float* Wl    = (const float*)d_in[10];
    const float* bl    = (const float*)d_in[11];
    float* out = (float*)d_out;

    k_mega<<<NBLK, NTHR>>>(x_idx, emb, Wih, bih, bhh, Whh, Wm,
                           Wf, bf, bm, Wl, bl, out);
}

// round 11
// speedup vs baseline: 1.3404x; 1.3404x over previous
#include <cuda_runtime.h>
#include <cuda_fp16.h>

#define HID 256
#define G4  1024
#define NE  64
#define BAT 256
#define NSTEP 6
#define RK  16

// ---------------- scratch (allocation-free: device globals) ----------------
__device__ __align__(16) float   g_xg[NE * G4];      // fp32 gate-interleaved [j][k][4]
__device__ __align__(16) uint2   g_xgh[NE * HID];    // fp16 (i,f)(g,o) packed, 8B per (j,k)
__device__ __align__(16) __half2 g_whh2[128 * G4];   // PW[kp][m] = (WhhT[2kp][m], WhhT[2kp+1][m])
__device__ __align__(16) __half2 g_wm2[128 * HID];   // PM[kp][m]
__device__ __align__(16) float   g_h0[NE * HID];
__device__ __align__(16) float   g_c0[NE * HID];
__device__ __align__(16) float   g_sout[NE * RK];

// ---------------- transcendentals: single-MUFU tanh.approx -----------------
__device__ __forceinline__ float tap(float x){ float y; asm("tanh.approx.f32 %0,%1;" : "=f"(y) : "f"(x)); return y; }
__device__ __forceinline__ float frcp(float x){ float y; asm("rcp.approx.f32 %0,%1;" : "=f"(y) : "f"(x)); return y; }
__device__ __forceinline__ float sigm(float x){ return fmaf(0.5f, tap(0.5f * x), 0.5f); }
__device__ __forceinline__ float2 h2f(__half2 h){ return __half22float2(h); }

// ============================================================================
// K_prep: blocks 0..31  -> xg GEMM (As-preload + reg-prefetched Bs chunks)
//         blocks 32..95 -> Whh -> g_whh2  (64x64 tiles, fp16 k-pair pack)
//         blocks 96..111-> Wm  -> g_wm2
// emb tile preloaded once (fp16), Wih streamed in 4 chunks of 64k with the
// NEXT chunk's float4s issued into registers before computing the current
// chunk -> DRAM latency overlapped with 512 FMA/thread of compute.
// ============================================================================
__global__ __launch_bounds__(256) void k_prep(const float* __restrict__ emb,
                                              const float* __restrict__ Wih,
                                              const float* __restrict__ bih,
                                              const float* __restrict__ bhh,
                                              const float* __restrict__ Whh,
                                              const float* __restrict__ Wm)
{
    __shared__ __align__(16) union {
        struct { __half As[256][34]; float Bs[64][68]; } g;  // 17.4KB + 17.4KB
        float T[64 * 65];                                    // 16.6KB
    } SP;
    const int id = blockIdx.x, t = threadIdx.x;

    if (id < 32) {
        const int tx = t & 15, ty = t >> 4;
        const int jb0 = (id & 1) * 32;
        const int m0  = (id >> 1) * 64;

        // ---- As preload: emb[jb0..+32][0..256] -> As[k][j] (fp16) ----
        {
            const int jrow = t >> 3;             // 0..31
            const int c0 = (t & 7) * 32;         // 0..224
            #pragma unroll
            for (int i = 0; i < 8; i++) {
                const float4 v = *(const float4*)&emb[(jb0 + jrow) * HID + c0 + 4 * i];
                SP.g.As[c0 + 4*i + 0][jrow] = __float2half(v.x);
                SP.g.As[c0 + 4*i + 1][jrow] = __float2half(v.y);
                SP.g.As[c0 + 4*i + 2][jrow] = __float2half(v.z);
                SP.g.As[c0 + 4*i + 3][jrow] = __float2half(v.w);
            }
        }

        // ---- Bs chunk 0 prefetch (4 float4/thread in flight) ----
        const int br = t >> 4;                   // 0..15 (row base)
        const int bc4 = (t & 15) * 4;            // 0..60 (k offset)
        float4 pf0, pf1, pf2, pf3;
        {
            pf0 = *(const float4*)&Wih[(m0 + br +  0) * HID + bc4];
            pf1 = *(const float4*)&Wih[(m0 + br + 16) * HID + bc4];
            pf2 = *(const float4*)&Wih[(m0 + br + 32) * HID + bc4];
            pf3 = *(const float4*)&Wih[(m0 + br + 48) * HID + bc4];
        }

        float acc[2][4] = {};
        for (int ch = 0; ch < 4; ch++) {
            // store current chunk (transposed Bs[k][m])
            SP.g.Bs[bc4+0][br+ 0] = pf0.x; SP.g.Bs[bc4+1][br+ 0] = pf0.y;
            SP.g.Bs[bc4+2][br+ 0] = pf0.z; SP.g.Bs[bc4+3][br+ 0] = pf0.w;
            SP.g.Bs[bc4+0][br+16] = pf1.x; SP.g.Bs[bc4+1][br+16] = pf1.y;
            SP.g.Bs[bc4+2][br+16] = pf1.z; SP.g.Bs[bc4+3][br+16] = pf1.w;
            SP.g.Bs[bc4+0][br+32] = pf2.x; SP.g.Bs[bc4+1][br+32] = pf2.y;
            SP.g.Bs[bc4+2][br+32] = pf2.z; SP.g.Bs[bc4+3][br+32] = pf2.w;
            SP.g.Bs[bc4+0][br+48] = pf3.x; SP.g.Bs[bc4+1][br+48] = pf3.y;
            SP.g.Bs[bc4+2][br+48] = pf3.z; SP.g.Bs[bc4+3][br+48] = pf3.w;
            // issue next chunk's loads NOW (overlap with compute below)
            if (ch < 3) {
                const int kb = 64 * (ch + 1);
                pf0 = *(const float4*)&Wih[(m0 + br +  0) * HID + kb + bc4];
                pf1 = *(const float4*)&Wih[(m0 + br + 16) * HID + kb + bc4];
                pf2 = *(const float4*)&Wih[(m0 + br + 32) * HID + kb + bc4];
                pf3 = *(const float4*)&Wih[(m0 + br + 48) * HID + kb + bc4];
            }
            __syncthreads();          // Bs (and, first iter, As) visible
            const int kg = 64 * ch;
            #pragma unroll 8
            for (int kk = 0; kk < 64; kk++) {
                const float2 a = h2f(*(const __half2*)&SP.g.As[kg + kk][2 * ty]);
                const float4 bv = *(const float4*)&SP.g.Bs[kk][4 * tx];
                acc[0][0] = fmaf(a.x, bv.x, acc[0][0]); acc[0][1] = fmaf(a.x, bv.y, acc[0][1]);
                acc[0][2] = fmaf(a.x, bv.z, acc[0][2]); acc[0][3] = fmaf(a.x, bv.w, acc[0][3]);
                acc[1][0] = fmaf(a.y, bv.x, acc[1][0]); acc[1][1] = fmaf(a.y, bv.y, acc[1][1]);
                acc[1][2] = fmaf(a.y, bv.z, acc[1][2]); acc[1][3] = fmaf(a.y, bv.w, acc[1][3]);
            }
            __syncthreads();          // compute done before Bs overwrite
        }

        const int mc0 = m0 + 4 * tx;
        const int gate = mc0 >> 8;
        const int kc0  = mc0 & 255;
        float bias[4];
        #pragma unroll
        for (int jj = 0; jj < 4; jj++) bias[jj] = bih[mc0 + jj] + bhh[mc0 + jj];
        #pragma unroll
        for (int i = 0; i < 2; i++) {
            const int jr = jb0 + 2 * ty + i;
            #pragma unroll
            for (int jj = 0; jj < 4; jj++)
                g_xg[jr * G4 + 4 * (kc0 + jj) + gate] = acc[i][jj] + bias[jj];
        }
    } else {
        const bool isWhh = (id < 96);
        const int tid = isWhh ? (id - 32) : (id - 96);
        const int mi  = isWhh ? (tid & 15) : (tid & 3);   // 64-row m-tile index
        const int ki  = isWhh ? (tid >> 4) : (tid >> 2);  // 64-col k-tile index
        const float* __restrict__ src = isWhh ? Whh : Wm;
        {
            const int c4 = (t & 15) * 4;
            const int r0 = t >> 4;
            const float4 v0 = *(const float4*)&src[(mi * 64 + r0 +  0) * HID + ki * 64 + c4];
            const float4 v1 = *(const float4*)&src[(mi * 64 + r0 + 16) * HID + ki * 64 + c4];
            const float4 v2 = *(const float4*)&src[(mi * 64 + r0 + 32) * HID + ki * 64 + c4];
            const float4 v3 = *(const float4*)&src[(mi * 64 + r0 + 48) * HID + ki * 64 + c4];
            float* T0 = SP.T + (r0 +  0) * 65; float* T1 = SP.T + (r0 + 16) * 65;
            float* T2 = SP.T + (r0 + 32) * 65; float* T3 = SP.T + (r0 + 48) * 65;
            T0[c4+0] = v0.x; T0[c4+1] = v0.y; T0[c4+2] = v0.z; T0[c4+3] = v0.w;
            T1[c4+0] = v1.x; T1[c4+1] = v1.y; T1[c4+2] = v1.z; T1[c4+3] = v1.w;
            T2[c4+0] = v2.x; T2[c4+1] = v2.y; T2[c4+2] = v2.z; T2[c4+3] = v2.w;
            T3[c4+0] = v3.x; T3[c4+1] = v3.y; T3[c4+2] = v3.z; T3[c4+3] = v3.w;
        }
        __syncthreads();
        const int m_l = t & 63, kp0 = t >> 6;
        const int rowlen = isWhh ? G4 : HID;
        __half2* __restrict__ dst = isWhh ? g_whh2 : g_wm2;
        #pragma unroll
        for (int i = 0; i < 8; i++) {
            const int kpl = kp0 + 4 * i;
            const __half2 h2 = __floats2half2_rn(SP.T[m_l * 65 + 2 * kpl], SP.T[m_l * 65 + 2 * kpl + 1]);
            dst[(ki * 32 + kpl) * rowlen + mi * 64 + m_l] = h2;
        }
    }
}

// ============================================================================
// K_h0: grid 64: h0/c0 = cell(xg, c=0); sout = h0@Wf^T + bf; emit fp16 xg.
// ============================================================================
__global__ __launch_bounds__(256) void k_h0(const float* __restrict__ Wf,
                                            const float* __restrict__ bf)
{
    __shared__ float sh0[HID];
    const int j = blockIdx.x, t = threadIdx.x;
    const float4 x4 = ((const float4*)g_xg)[j * HID + t];   // (i,f,g,o)
    {
        union { __half2 h2[2]; uint2 u; } p;
        p.h2[0] = __floats2half2_rn(x4.x, x4.y);
        p.h2[1] = __floats2half2_rn(x4.z, x4.w);
        g_xgh[j * HID + t] = p.u;
    }
    const float c0 = sigm(x4.x) * tap(x4.z);
    const float h0 = sigm(x4.w) * tap(c0);
    g_c0[j * HID + t] = c0;
    g_h0[j * HID + t] = h0;
    sh0[t] = h0;
    __syncthreads();
    const int w = t >> 5, l = t & 31;
    #pragma unroll
    for (int rr = 0; rr < 2; rr++) {
        const int r = w + 8 * rr;
        float a = 0.f;
        #pragma unroll
        for (int q = 0; q < 8; q++) {
            const int k = l + 32 * q;
            a = fmaf(sh0[k], Wf[r * HID + k], a);
        }
        a += __shfl_xor_sync(0xFFFFFFFFu, a, 16);
        a += __shfl_xor_sync(0xFFFFFFFFu, a, 8);
        a += __shfl_xor_sync(0xFFFFFFFFu, a, 4);
        a += __shfl_xor_sync(0xFFFFFFFFu, a, 2);
        a += __shfl_xor_sync(0xFFFFFFFFu, a, 1);
        if (l == 0) g_sout[j * RK + r] = a + bf[r];
    }
}

// ============================================================================
// K_chain: 128 blocks x 512 thr (byte-identical to the round-7 124.7us kernel)
// ============================================================================
__global__ __launch_bounds__(512) void k_chain(const int* __restrict__ xidx,
                                               const float* __restrict__ bm,
                                               const float* __restrict__ Wl,
                                               const float* __restrict__ bl,
                                               float* __restrict__ out)
{
    __shared__ __align__(16) float sh_h[2][HID];
    __shared__ __align__(16) float sh_c[2][HID];
    __shared__ __align__(16) float sh_hgp[2][2][G4];   // GEMV partials; [0] = combined hg
    __shared__ __align__(16) float s_cur[2][HID];
    __shared__ float st_tot[2][RK];
    __shared__ float s_rcl[RK];

    const int t = threadIdx.x;
    const int half = t >> 8, tt = t & 255;
    const int b0 = blockIdx.x * 2;
    float* s_hs = &sh_hgp[1][0][0];         // hsum partials / combined
    float* s_md = &sh_hgp[0][0][0];         // mid partials (hg dead)

    // ---- Phase A: step-0 normalize + gather ----
    if (t < RK) {
        float s = 0.f;
        #pragma unroll 8
        for (int j = 0; j < NE; j++) s += g_sout[j * RK + t];
        s_rcl[t] = 1.0f / s;
    }
    {
        const int sel = xidx[(b0 + half) * NSTEP + 0];
        sh_h[half][tt] = g_h0[sel * HID + tt];
        sh_c[half][tt] = g_c0[sel * HID + tt];
    }
    __syncthreads();
    if (t < 2 * RK) {
        const int b = t >> 4, r = t & 15;
        const int sel = xidx[(b0 + b) * NSTEP + 0];
        st_tot[b][r] = g_sout[sel * RK + r] * s_rcl[r];
    }

    for (int s = 1; s < NSTEP; s++) {
        __syncthreads();
        // ---- GEMV: hg[b][m] = sum_k h[b][k]*WhhT[k][m]; kp-split by half ----
        {
            const int kpb = half * 64;             // 64 kp = 128 k per half
            const int mb  = tt * 4;
            float4 ac0 = {0,0,0,0}, ac1 = {0,0,0,0};
            #pragma unroll 4
            for (int kp = 0; kp < 64; kp++) {
                const uint4 w = *(const uint4*)&g_whh2[(kpb + kp) * G4 + mb];
                const float2 hA = *(const float2*)&sh_h[0][2 * (kpb + kp)];
                const float2 hB = *(const float2*)&sh_h[1][2 * (kpb + kp)];
                const float2 p0 = h2f(*(const __half2*)&w.x);
                const float2 p1 = h2f(*(const __half2*)&w.y);
                const float2 p2 = h2f(*(const __half2*)&w.z);
                const float2 p3 = h2f(*(const __half2*)&w.w);
                ac0.x = fmaf(hA.x, p0.x, fmaf(hA.y, p0.y, ac0.x));
                ac0.y = fmaf(hA.x, p1.x, fmaf(hA.y, p1.y, ac0.y));
                ac0.z = fmaf(hA.x, p2.x, fmaf(hA.y, p2.y, ac0.z));
                ac0.w = fmaf(hA.x, p3.x, fmaf(hA.y, p3.y, ac0.w));
                ac1.x = fmaf(hB.x, p0.x, fmaf(hB.y, p0.y, ac1.x));
                ac1.y = fmaf(hB.x, p1.x, fmaf(hB.y, p1.y, ac1.y));
                ac1.z = fmaf(hB.x, p2.x, fmaf(hB.y, p2.y, ac1.z));
                ac1.w = fmaf(hB.x, p3.x, fmaf(hB.y, p3.y, ac1.w));
            }
            *(float4*)&sh_hgp[half][0][mb] = ac0;
            *(float4*)&sh_hgp[half][1][mb] = ac1;
        }
        __syncthreads();
        {   // combine k-halves: 2048 floats, 4 per thread
            const int lin = t * 4;
            float4 a = *(const float4*)(&sh_hgp[0][0][0] + lin);
            const float4 b = *(const float4*)(&sh_hgp[1][0][0] + lin);
            a.x += b.x; a.y += b.y; a.z += b.z; a.w += b.w;
            *(float4*)(&sh_hgp[0][0][0] + lin) = a;
        }
        __syncthreads();
        // ---- CELL: j-split by half (32 j each), k = tt ----
        const int selb0 = xidx[b0 * NSTEP + s];
        const int selb1 = xidx[(b0 + 1) * NSTEP + s];
        const int k = tt;
        const float hgI0 = sh_hgp[0][0][k],         hgF0 = sh_hgp[0][0][HID + k];
        const float hgG0 = sh_hgp[0][0][2*HID + k], hgO0 = sh_hgp[0][0][3*HID + k];
        const float hgI1 = sh_hgp[0][1][k],         hgF1 = sh_hgp[0][1][HID + k];
        const float hgG1 = sh_hgp[0][1][2*HID + k], hgO1 = sh_hgp[0][1][3*HID + k];
        const float cp0 = sh_c[0][k], cp1 = sh_c[1][k];
        __syncthreads();   // reads of sh_c / gates done before owners overwrite
        float hs0 = 0.f, hs1 = 0.f, hv0 = 0.f, cv0 = 0.f, hv1 = 0.f, cv1 = 0.f;
        const int jb = half * 32;
        #pragma unroll 4
        for (int j = jb; j < jb + 32; j++) {
            const uint2 u = g_xgh[j * HID + k];
            const float2 vif = h2f(*(const __half2*)&u.x);   // (i,f)
            const float2 vgo = h2f(*(const __half2*)&u.y);   // (g,o)
            {
                const float iv = sigm(vif.x + hgI0);
                const float fv = sigm(vif.y + hgF0);
                const float gv = tap (vgo.x + hgG0);
                const float ov = sigm(vgo.y + hgO0);
                const float cn = fmaf(fv, cp0, iv * gv);
                const float hn = ov * tap(cn);
                hs0 += hn;
                if (j == selb0) { hv0 = hn; cv0 = cn; }
            }
            {
                const float iv = sigm(vif.x + hgI1);
                const float fv = sigm(vif.y + hgF1);
                const float gv = tap (vgo.x + hgG1);
                const float ov = sigm(vgo.y + hgO1);
                const float cn = fmaf(fv, cp1, iv * gv);
                const float hn = ov * tap(cn);
                hs1 += hn;
                if (j == selb1) { hv1 = hn; cv1 = cn; }
            }
        }
        s_hs[(half * 2 + 0) * HID + k] = hs0;
        s_hs[(half * 2 + 1) * HID + k] = hs1;
        if ((selb0 >> 5) == half) { sh_h[0][k] = hv0; sh_c[0][k] = cv0; }
        if ((selb1 >> 5) == half) { sh_h[1][k] = hv1; sh_c[1][k] = cv1; }
        __syncthreads();
        {   // combine hsum halves
            const int b = t >> 8, k2 = t & 255;
            s_hs[b * HID + k2] += s_hs[(2 + b) * HID + k2];
        }
        __syncthreads();

        if (s < NSTEP - 1) {
            // ---- MID: num/den GEMV vs WmT (kp-split), total @= cur ----
            const int kpb = half * 64;
            const int m = tt;
            float n0 = 0.f, n1 = 0.f, d0 = 0.f, d1 = 0.f;
            #pragma unroll 4
            for (int kp = 0; kp < 64; kp++) {
                const float2 w = h2f(g_wm2[(kpb + kp) * HID + m]);
                const float2 hA = *(const float2*)&sh_h[0][2 * (kpb + kp)];
                const float2 hB = *(const float2*)&sh_h[1][2 * (kpb + kp)];
                const float2 uA = *(const float2*)&s_hs[0 * HID + 2 * (kpb + kp)];
                const float2 uB = *(const float2*)&s_hs[1 * HID + 2 * (kpb + kp)];
                n0 = fmaf(w.x, hA.x, fmaf(w.y, hA.y, n0));
                n1 = fmaf(w.x, hB.x, fmaf(w.y, hB.y, n1));
                d0 = fmaf(w.x, uA.x, fmaf(w.y, uA.y, d0));
                d1 = fmaf(w.x, uB.x, fmaf(w.y, uB.y, d1));
            }
            s_md[(half * 4 + 0) * HID + m] = n0;
            s_md[(half * 4 + 1) * HID + m] = n1;
            s_md[(half * 4 + 2) * HID + m] = d0;
            s_md[(half * 4 + 3) * HID + m] = d1;
            __syncthreads();
            if (half == 0) {
                const float n0f = s_md[0 * HID + tt] + s_md[4 * HID + tt];
                const float n1f = s_md[1 * HID + tt] + s_md[5 * HID + tt];
                const float d0f = s_md[2 * HID + tt] + s_md[6 * HID + tt];
                const float d1f = s_md[3 * HID + tt] + s_md[7 * HID + tt];
                const float bmv = bm[tt];
                s_cur[0][tt] = (n0f + bmv) * frcp(d0f + 64.0f * bmv);
                s_cur[1][tt] = (n1f + bmv) * frcp(d1f + 64.0f * bmv);
            }
            __syncthreads();
            float ntot = 0.f;
            const int ub = t >> 4, ur = t & 15;
            if (t < 32) {
                #pragma unroll
                for (int r1 = 0; r1 < RK; r1++)
                    ntot = fmaf(st_tot[ub][r1], s_cur[ub][r1 * RK + ur], ntot);
            }
            __syncthreads();
            if (t < 32) st_tot[ub][ur] = ntot;
        } else {
            // ---- FINAL ----
            if (t < 64) {
                const int b = t >> 5, l = t & 31;
                const int r = l & 15, role = l >> 4;
                const float* __restrict__ src = role ? (s_hs + b * HID) : &sh_h[b][0];
                float acc = 0.f;
                #pragma unroll 8
                for (int kk = 0; kk < HID; kk++)
                    acc = fmaf(Wl[r * HID + kk], src[kk], acc);
                acc += (role ? 64.0f : 1.0f) * bl[r];
                const float den = __shfl_down_sync(0xFFFFFFFFu, acc, 16);
                float v = 0.f;
                if (!role) v = st_tot[b][r] * acc * frcp(den);
                v += __shfl_xor_sync(0xFFFFFFFFu, v, 8);
                v += __shfl_xor_sync(0xFFFFFFFFu, v, 4);
                v += __shfl_xor_sync(0xFFFFFFFFu, v, 2);
                v += __shfl_xor_sync(0xFFFFFFFFu, v, 1);
                if (l == 0) out[b0 + b] = v;
            }
        }
    }
}

// ============================================================================
extern "C" void kernel_launch(void* const* d_in, const int* in_sizes, int n_in,
                              void* d_out, int out_size)
{
    (void)in_sizes; (void)n_in; (void)out_size;
    const int*   x_idx = (const int*)  d_in[0];
    const float* emb   = (const float*)d_in[1];
    const float* Wih   = (const float*)d_in[2];
    const float* Whh   = (const float*)d_in[3];
    const float* bih   = (const float*)d_in[4];
    const float* bhh   = (const float*)d_in[5];
    const float* Wf    = (const float*)d_in[6];
    const float* bf    = (const float*)d_in[7];
    const float* Wm    = (const float*)d_in[8];
    const float* bm    = (const float*)d_in[9];
    const float* Wl    = (const float*)d_in[10];
    const float* bl    = (const float*)d_in[11];
    float* out = (float*)d_out;

    k_prep <<<112, 256>>>(emb, Wih, bih, bhh, Whh, Wm);
    k_h0   <<<NE, 256>>>(Wf, bf);
    k_chain<<<BAT / 2, 512>>>(x_idx, bm, Wl, bl, out);
}